// round 13
// baseline (speedup 1.0000x reference)
#include <cuda_runtime.h>
#include <cuda_bf16.h>
#include <math.h>
#include <stdint.h>

#define BB 4
#define DD 256
#define LL 4096
#define NN (BB*LL)      // 16384 tokens
#define KK 8192
#define EPSF 1e-12f
#define MARGIN 0.03f          // fp8 rescue margin (unscaled sims)
#define F8SCALE 16.0f         // per-side scale -> dots scaled by 256

#define KSPLIT 16
#define CPS (KK/KSPLIT)        // 512 codes per slice
#define NCAND (KSPLIT*3)       // 48 candidates per token

// ---- GEMM tiling ----
#define BM 128
#define BN 128
#define SLK 144                 // smem row stride bytes (conflict-free)
#define STAGE 18432             // 128 rows x 144 B (one operand, one k-half)
#define SA_BYTES (2*STAGE)      // A resident: both k-halves
#define SB_OFF SA_BYTES         // B ring base
#define NSTAGES 8               // 4 chunks x 2 k-halves
#define GSMEM (SA_BYTES + 3*STAGE)   // 92160

// ---- device scratch ----
__device__ float    g_cbn[KK*DD];     // normalized codebook fp32 (8 MB)
__device__ float    g_xn[NN*DD];      // normalized tokens fp32 (16 MB)
__device__ uint8_t  g_c8[KK*DD];      // fp8 e4m3 codebook *16 (2 MB)
__device__ uint8_t  g_x8[NN*DD];      // fp8 e4m3 tokens *16 (4 MB)
__device__ float    g_norm[NN];
__device__ float    g_candv[NN*NCAND];
__device__ int      g_candi[NN*NCAND];
__device__ double   g_acc;
__device__ unsigned g_done = 0;

// ------------------------------------------------------------------
// result: low byte = e4m3(lo), high byte = e4m3(hi)
__device__ __forceinline__ uint16_t pack_e4m3x2(float lo, float hi) {
    uint16_t r;
    asm("cvt.rn.satfinite.e4m3x2.f32 %0, %1, %2;" : "=h"(r) : "f"(hi), "f"(lo));
    return r;
}

#define LDMATRIX_X4(r0, r1, r2, r3, addr) \
    asm volatile("ldmatrix.sync.aligned.m8n8.x4.shared.b16 {%0,%1,%2,%3}, [%4];" \
        : "=r"(r0), "=r"(r1), "=r"(r2), "=r"(r3) : "r"(addr))

// ------------------------------------------------------------------
// merged prep: blocks [0,1024) normalize codebook rows; blocks [1024,1536)
// transpose+normalize token tiles. One launch, both halves run concurrently.
__global__ void prep_kernel(const float* __restrict__ cb,
                            const float* __restrict__ x) {
    int tid = threadIdx.x, wid = tid >> 5, lane = tid & 31;
    if (blockIdx.x < 1024) {
        if (blockIdx.x == 0 && tid == 0) g_acc = 0.0;
        int row = blockIdx.x * 8 + wid;
        const float4* src = (const float4*)(cb + (size_t)row * DD);
        float4 v0 = src[lane];
        float4 v1 = src[lane + 32];
        float ss = v0.x*v0.x + v0.y*v0.y + v0.z*v0.z + v0.w*v0.w
                 + v1.x*v1.x + v1.y*v1.y + v1.z*v1.z + v1.w*v1.w;
        #pragma unroll
        for (int o = 16; o; o >>= 1) ss += __shfl_xor_sync(~0u, ss, o);
        float inv = 1.0f / fmaxf(sqrtf(ss), EPSF);
        v0.x*=inv; v0.y*=inv; v0.z*=inv; v0.w*=inv;
        v1.x*=inv; v1.y*=inv; v1.z*=inv; v1.w*=inv;
        float4* dst = (float4*)(g_cbn + (size_t)row * DD);
        dst[lane] = v0; dst[lane + 32] = v1;
        uint32_t u0 = (uint32_t)pack_e4m3x2(v0.x*F8SCALE, v0.y*F8SCALE)
                    | ((uint32_t)pack_e4m3x2(v0.z*F8SCALE, v0.w*F8SCALE) << 16);
        uint32_t u1 = (uint32_t)pack_e4m3x2(v1.x*F8SCALE, v1.y*F8SCALE)
                    | ((uint32_t)pack_e4m3x2(v1.z*F8SCALE, v1.w*F8SCALE) << 16);
        uint32_t* h8 = (uint32_t*)(g_c8 + (size_t)row * DD);
        h8[lane] = u0; h8[lane + 32] = u1;
    } else {
        __shared__ float tile[32][261];
        int q = blockIdx.x - 1024;          // 0..511
        int b = q >> 7, l0 = (q & 127) * 32;
        #pragma unroll
        for (int j = 0; j < 32; j++) {
            int d = wid * 32 + j;
            tile[lane][d] = x[(size_t)b * DD * LL + (size_t)d * LL + l0 + lane];
        }
        __syncthreads();
        #pragma unroll
        for (int i = 0; i < 4; i++) {
            int t = wid * 4 + i;
            int n = b * LL + l0 + t;
            float ss = 0.0f;
            #pragma unroll
            for (int j = 0; j < 8; j++) { float v = tile[t][lane + 32*j]; ss = fmaf(v, v, ss); }
            #pragma unroll
            for (int o = 16; o; o >>= 1) ss += __shfl_xor_sync(~0u, ss, o);
            float nrm = fmaxf(sqrtf(ss), EPSF);
            float inv = 1.0f / nrm;
            if (lane == 0) g_norm[n] = nrm;
            #pragma unroll
            for (int j = 0; j < 8; j++) {
                int d = lane + 32*j;
                float v = tile[t][d] * inv;
                g_xn[(size_t)n * DD + d] = v;
                g_x8[(size_t)n * DD + d] = (uint8_t)(pack_e4m3x2(v*F8SCALE, 0.0f) & 0xFF);
            }
        }
    }
}

// ------------------------------------------------------------------
#define CP_ASYNC16(dst, src) \
    asm volatile("cp.async.cg.shared.global [%0], [%1], 16;\n" :: "r"(dst), "l"(src))

// A: both k-halves, loaded once (8 cp.async per thread)
__device__ __forceinline__ void load_A(uint32_t sb, int mbase, int tid) {
    #pragma unroll
    for (int h = 0; h < 2; h++)
        #pragma unroll
        for (int i = 0; i < 4; i++) {
            int idx = tid + i * 256;
            int row = idx >> 3, c = (idx & 7) * 16;
            CP_ASYNC16(sb + h * STAGE + row * SLK + c,
                       g_x8 + (size_t)(mbase + row) * DD + h * 128 + c);
        }
}

// B stage s -> ring slot r (4 cp.async per thread)
__device__ __forceinline__ void load_B(int s, int r, uint32_t sb,
                                       int slice, int tid) {
    int kb = (s & 1) * 128;
    int kc = s >> 1;
    const uint8_t* src = g_c8 + (size_t)(slice * CPS + kc * BN) * DD + kb;
    uint32_t dst = sb + SB_OFF + r * STAGE;
    #pragma unroll
    for (int i = 0; i < 4; i++) {
        int idx = tid + i * 256;
        int row = idx >> 3, c = (idx & 7) * 16;
        CP_ASYNC16(dst + row * SLK + c, src + (size_t)row * DD + c);
    }
}

// fused fp8 mma GEMM + per-(token,slice) packed top-3; ldmatrix feed.
// A resident in smem; B 3-slot ring. grid = (KSPLIT, NN/BM).
// (mainloop identical to the round-9/11/12 best — at the mma.sync floor)
__global__ void __launch_bounds__(256, 2) gemm_topk_kernel() {
    extern __shared__ uint8_t sm[];
    uint32_t sb = (uint32_t)__cvta_generic_to_shared(sm);
    int tid = threadIdx.x;
    int wid = tid >> 5, lane = tid & 31;
    int warp_m = wid & 3, warp_n = wid >> 2;     // 4x2 warps: 32 rows x 64 cols
    int grp = lane >> 2, qid = lane & 3;
    int slice = blockIdx.x;
    int mbase = blockIdx.y * BM;

    int lt = lane >> 3, lr = lane & 7;
    uint32_t offA[2];
    #pragma unroll
    for (int mi = 0; mi < 2; mi++)
        offA[mi] = (uint32_t)((warp_m*32 + mi*16 + (lt & 1)*8 + lr) * SLK + (lt >> 1) * 16);
    uint32_t offB[4];
    #pragma unroll
    for (int p = 0; p < 4; p++)
        offB[p] = (uint32_t)((warp_n*64 + (2*p + (lt >> 1))*8 + lr) * SLK + (lt & 1) * 16);

    load_A(sb, mbase, tid);
    load_B(0, 0, sb, slice, tid);
    asm volatile("cp.async.commit_group;\n" ::);
    load_B(1, 1, sb, slice, tid);
    asm volatile("cp.async.commit_group;\n" ::);

    uint32_t t1[4], t2[4], t3[4];
    #pragma unroll
    for (int s4 = 0; s4 < 4; s4++) { t1[s4]=0; t2[s4]=0; t3[s4]=0; }

    float c[2][8][4];

    #pragma unroll 1
    for (int s = 0; s < NSTAGES; s++) {
        if ((s & 1) == 0) {
            #pragma unroll
            for (int mi = 0; mi < 2; mi++)
                #pragma unroll
                for (int ni = 0; ni < 8; ni++)
                    #pragma unroll
                    for (int j = 0; j < 4; j++) c[mi][ni][j] = 0.0f;
        }
        if (s < NSTAGES - 2) asm volatile("cp.async.wait_group 1;\n" ::);
        else                 asm volatile("cp.async.wait_group 0;\n" ::);
        __syncthreads();
        if (s + 2 < NSTAGES) {
            load_B(s + 2, (s + 2) % 3, sb, slice, tid);
            asm volatile("cp.async.commit_group;\n" ::);
        }

        uint32_t a_base = sb + (uint32_t)(s & 1) * STAGE;
        uint32_t b_base = sb + SB_OFF + (uint32_t)(s % 3) * STAGE;
        #pragma unroll
        for (int ks = 0; ks < 4; ks++) {
            uint32_t ksb = ks * 32;
            uint32_t a[2][4], b[8][2];
            #pragma unroll
            for (int mi = 0; mi < 2; mi++)
                LDMATRIX_X4(a[mi][0], a[mi][1], a[mi][2], a[mi][3],
                            a_base + offA[mi] + ksb);
            #pragma unroll
            for (int p = 0; p < 4; p++)
                LDMATRIX_X4(b[2*p][0], b[2*p][1], b[2*p+1][0], b[2*p+1][1],
                            b_base + offB[p] + ksb);
            #pragma unroll
            for (int mi = 0; mi < 2; mi++)
                #pragma unroll
                for (int ni = 0; ni < 8; ni++)
                    asm volatile(
                        "mma.sync.aligned.m16n8k32.row.col.f32.e4m3.e4m3.f32 "
                        "{%0,%1,%2,%3}, {%4,%5,%6,%7}, {%8,%9}, {%0,%1,%2,%3};\n"
                        : "+f"(c[mi][ni][0]), "+f"(c[mi][ni][1]),
                          "+f"(c[mi][ni][2]), "+f"(c[mi][ni][3])
                        : "r"(a[mi][0]), "r"(a[mi][1]), "r"(a[mi][2]), "r"(a[mi][3]),
                          "r"(b[ni][0]), "r"(b[ni][1]));
        }

        if (s & 1) {   // chunk kc = s>>1 complete: update packed top-3
            int kc = s >> 1;
            #pragma unroll
            for (int s4 = 0; s4 < 4; s4++) {
                int mi = s4 >> 1, h = s4 & 1;
                float m0 = -1e30f;
                #pragma unroll
                for (int ni = 0; ni < 8; ni++)
                    m0 = fmaxf(m0, fmaxf(c[mi][ni][h*2], c[mi][ni][h*2+1]));
                if ((__float_as_uint(m0 + 512.0f) | 0x1FFu) >= t3[s4]) {
                    #pragma unroll
                    for (int ni = 0; ni < 8; ni++)
                        #pragma unroll
                        for (int j = 0; j < 2; j++) {
                            float v = c[mi][ni][h*2 + j];
                            uint32_t col = kc*128 + warp_n*64 + ni*8 + qid*2 + j;
                            uint32_t u = (__float_as_uint(v + 512.0f) & 0xFFFFFE00u)
                                       | (511u - col);
                            if (u > t1[s4])      { t3[s4]=t2[s4]; t2[s4]=t1[s4]; t1[s4]=u; }
                            else if (u > t2[s4]) { t3[s4]=t2[s4]; t2[s4]=u; }
                            else if (u > t3[s4]) { t3[s4]=u; }
                        }
                }
            }
        }
    }

    __syncthreads();
    uint32_t* mk = (uint32_t*)sm;      // [128][24]
    #pragma unroll
    for (int s4 = 0; s4 < 4; s4++) {
        int row = warp_m*32 + (s4>>1)*16 + (s4&1)*8 + grp;
        int base2 = row * 24 + (warp_n*4 + qid) * 3;
        mk[base2+0] = t1[s4]; mk[base2+1] = t2[s4]; mk[base2+2] = t3[s4];
    }
    __syncthreads();
    if (tid < 128) {
        uint32_t b1=0, b2=0, b3=0;
        #pragma unroll
        for (int s2 = 0; s2 < 24; s2++) {
            uint32_t u = mk[tid*24 + s2];
            if (u > b1)      { b3=b2; b2=b1; b1=u; }
            else if (u > b2) { b3=b2; b2=u; }
            else if (u > b3) { b3=u; }
        }
        int n = mbase + tid;
        int base2 = n * NCAND + slice * 3;
        uint32_t ks_[3] = {b1, b2, b3};
        #pragma unroll
        for (int j = 0; j < 3; j++) {
            uint32_t u = ks_[j];
            g_candv[base2+j] = (__uint_as_float(u & 0xFFFFFE00u) - 512.0f) * (1.0f/256.0f);
            g_candi[base2+j] = slice * CPS + (int)(511u - (u & 0x1FFu));
        }
    }
}

// ------------------------------------------------------------------
// fused: margin rescue in rotation layout (winner row kept in regs; no q0
// gather) -> rotation -> commit loss -> transposed write -> last-block loss.
// 1024 threads: ONE warp per token (32 tokens per block).
__global__ void __launch_bounds__(1024) rotate_out_kernel(float* __restrict__ out,
                                                          int out_size) {
    __shared__ float tile[256][33];
    int b = blockIdx.y, l0 = blockIdx.x * 32;
    int tid = threadIdx.x, wid = tid >> 5, lane = tid & 31;

    int t = wid;                       // token slot within the 32-token tile
    int n = b * LL + l0 + t;

    const float4* xp = (const float4*)(g_xn + (size_t)n * DD);
    float4 x0 = xp[lane], x1 = xp[lane + 32];
    float nrm = g_norm[n];

    float va = g_candv[n*NCAND + lane];
    int   ka = g_candi[n*NCAND + lane];
    float vb = (lane < 16) ? g_candv[n*NCAND + 32 + lane] : -3.0f;
    int   kb = (lane < 16) ? g_candi[n*NCAND + 32 + lane] : 0x7fffffff;
    float rmax = fmaxf(va, vb);
    #pragma unroll
    for (int o = 16; o; o >>= 1) rmax = fmaxf(rmax, __shfl_xor_sync(~0u, rmax, o));
    float thr = rmax - MARGIN;

    unsigned m1 = __ballot_sync(~0u, va >= thr);
    unsigned m2 = __ballot_sync(~0u, vb >= thr);   // >=1 survivor always

    // rescore every survivor in ROTATION layout; keep best row in registers
    float bestv = -3.0f; int besti = 0x7fffffff;
    float4 q0 = make_float4(0,0,0,0), q1 = make_float4(0,0,0,0);
    while (m1 | m2) {
        int k0, k1 = -1;
        if (m1) { int ci = __ffs(m1) - 1; m1 &= m1 - 1; k0 = __shfl_sync(~0u, ka, ci); }
        else    { int ci = __ffs(m2) - 1; m2 &= m2 - 1; k0 = __shfl_sync(~0u, kb, ci); }
        if (m1)      { int ci = __ffs(m1) - 1; m1 &= m1 - 1; k1 = __shfl_sync(~0u, ka, ci); }
        else if (m2) { int ci = __ffs(m2) - 1; m2 &= m2 - 1; k1 = __shfl_sync(~0u, kb, ci); }

        const float4* cp0 = (const float4*)(g_cbn + (size_t)k0 * DD);
        float4 c00 = cp0[lane], c01 = cp0[lane + 32];
        float d0 = x0.x*c00.x + x0.y*c00.y + x0.z*c00.z + x0.w*c00.w
                 + x1.x*c01.x + x1.y*c01.y + x1.z*c01.z + x1.w*c01.w;
        float d1 = -3.0f;
        float4 c10, c11;
        if (k1 >= 0) {
            const float4* cp1 = (const float4*)(g_cbn + (size_t)k1 * DD);
            c10 = cp1[lane]; c11 = cp1[lane + 32];
            d1 = x0.x*c10.x + x0.y*c10.y + x0.z*c10.z + x0.w*c10.w
               + x1.x*c11.x + x1.y*c11.y + x1.z*c11.z + x1.w*c11.w;
        }
        #pragma unroll
        for (int o = 16; o; o >>= 1) {
            d0 += __shfl_xor_sync(~0u, d0, o);
            d1 += __shfl_xor_sync(~0u, d1, o);
        }
        if (d0 > bestv || (d0 == bestv && k0 < besti)) {
            bestv = d0; besti = k0; q0 = c00; q1 = c01;
        }
        if (k1 >= 0 && (d1 > bestv || (d1 == bestv && k1 < besti))) {
            bestv = d1; besti = k1; q0 = c10; q1 = c11;
        }
    }

    // rotation (q0/q1 already in registers — no gather)
    float s0x = x0.x + q0.x, s0y = x0.y + q0.y, s0z = x0.z + q0.z, s0w = x0.w + q0.w;
    float s1x = x1.x + q1.x, s1y = x1.y + q1.y, s1z = x1.z + q1.z, s1w = x1.w + q1.w;
    float ss = s0x*s0x + s0y*s0y + s0z*s0z + s0w*s0w
             + s1x*s1x + s1y*s1y + s1z*s1z + s1w*s1w;
    float xs = x0.x*s0x + x0.y*s0y + x0.z*s0z + x0.w*s0w
             + x1.x*s1x + x1.y*s1y + x1.z*s1z + x1.w*s1w;
    #pragma unroll
    for (int o = 16; o; o >>= 1) {
        ss += __shfl_xor_sync(~0u, ss, o);
        xs += __shfl_xor_sync(~0u, xs, o);
    }
    float sn = fmaxf(sqrtf(ss), EPSF);
    float cc = 2.0f * (xs / sn) / sn;

    float4 r0, r1;
    r0.x = x0.x - cc*s0x + 2.0f*q0.x;  r0.y = x0.y - cc*s0y + 2.0f*q0.y;
    r0.z = x0.z - cc*s0z + 2.0f*q0.z;  r0.w = x0.w - cc*s0w + 2.0f*q0.w;
    r1.x = x1.x - cc*s1x + 2.0f*q1.x;  r1.y = x1.y - cc*s1y + 2.0f*q1.y;
    r1.z = x1.z - cc*s1z + 2.0f*q1.z;  r1.w = x1.w - cc*s1w + 2.0f*q1.w;

    int d0i = lane * 4;
    tile[d0i+0][t] = r0.x; tile[d0i+1][t] = r0.y; tile[d0i+2][t] = r0.z; tile[d0i+3][t] = r0.w;
    tile[128+d0i+0][t] = r1.x; tile[128+d0i+1][t] = r1.y;
    tile[128+d0i+2][t] = r1.z; tile[128+d0i+3][t] = r1.w;

    float e0x = r0.x - x0.x*nrm, e0y = r0.y - x0.y*nrm, e0z = r0.z - x0.z*nrm, e0w = r0.w - x0.w*nrm;
    float e1x = r1.x - x1.x*nrm, e1y = r1.y - x1.y*nrm, e1z = r1.z - x1.z*nrm, e1w = r1.w - x1.w*nrm;
    float cs = e0x*e0x + e0y*e0y + e0z*e0z + e0w*e0w
             + e1x*e1x + e1y*e1y + e1z*e1z + e1w*e1w;
    #pragma unroll
    for (int o = 16; o; o >>= 1) cs += __shfl_xor_sync(~0u, cs, o);
    if (lane == 0) atomicAdd(&g_acc, (double)cs);

    __syncthreads();

    #pragma unroll
    for (int j = 0; j < 8; j++) {
        int d = wid * 8 + j;
        out[(size_t)b * DD * LL + (size_t)d * LL + l0 + lane] = tile[d][lane];
    }

    // last block writes the loss tail (graph-replay safe: counter resets)
    if (tid == 0) {
        __threadfence();
        unsigned old = atomicAdd(&g_done, 1u);
        if (old == 511u) {
            g_done = 0;
            __threadfence();
            long q = (long)BB * DD * LL;
            float loss = (float)(0.25 * g_acc / (double)((long)NN * DD));
            for (long i = q; i < (long)out_size; i++) out[i] = loss;
        }
    }
}

// ------------------------------------------------------------------
extern "C" void kernel_launch(void* const* d_in, const int* in_sizes, int n_in,
                              void* d_out, int out_size) {
    const float* x  = (const float*)d_in[0];   // [4,256,4096]
    const float* cb = (const float*)d_in[1];   // [8192,256]
    float* out = (float*)d_out;

    static int attr_set = 0;
    if (!attr_set) {
        cudaFuncSetAttribute(gemm_topk_kernel,
                             cudaFuncAttributeMaxDynamicSharedMemorySize, GSMEM);
        attr_set = 1;
    }

    prep_kernel<<<1536, 256>>>(cb, x);
    gemm_topk_kernel<<<dim3(KSPLIT, NN / BM), 256, GSMEM>>>();
    rotate_out_kernel<<<dim3(LL / 32, BB), 1024>>>(out, out_size);
}

// round 14
// speedup vs baseline: 1.0022x; 1.0022x over previous
#include <cuda_runtime.h>
#include <cuda_bf16.h>
#include <math.h>
#include <stdint.h>

#define BB 4
#define DD 256
#define LL 4096
#define NN (BB*LL)      // 16384 tokens
#define KK 8192
#define EPSF 1e-12f
#define MARGIN 0.03f          // fp8 rescue margin (unscaled sims)
#define F8SCALE 16.0f         // per-side scale -> dots scaled by 256

#define KSPLIT 16
#define CPS (KK/KSPLIT)        // 512 codes per slice
#define NCAND (KSPLIT*3)       // 48 candidates per token

// ---- GEMM tiling ----
#define BM 128
#define BN 128
#define SLK 144                 // smem row stride bytes (conflict-free)
#define STAGE 18432             // 128 rows x 144 B (one operand, one k-half)
#define SA_BYTES (2*STAGE)      // A resident: both k-halves
#define SB_OFF SA_BYTES         // B ring base
#define NSTAGES 8               // 4 chunks x 2 k-halves
#define GSMEM (SA_BYTES + 3*STAGE)   // 92160

// ---- device scratch ----
__device__ float    g_cbn[KK*DD];     // normalized codebook fp32 (8 MB)
__device__ float    g_xn[NN*DD];      // normalized tokens fp32 (16 MB)
__device__ uint8_t  g_c8[KK*DD];      // fp8 e4m3 codebook *16 (2 MB)
__device__ uint8_t  g_x8[NN*DD];      // fp8 e4m3 tokens *16 (4 MB)
__device__ float    g_norm[NN];
__device__ float    g_candv[NN*NCAND];
__device__ int      g_candi[NN*NCAND];
__device__ double   g_acc;
__device__ unsigned g_done = 0;

// ------------------------------------------------------------------
// result: low byte = e4m3(lo), high byte = e4m3(hi)
__device__ __forceinline__ uint16_t pack_e4m3x2(float lo, float hi) {
    uint16_t r;
    asm("cvt.rn.satfinite.e4m3x2.f32 %0, %1, %2;" : "=h"(r) : "f"(hi), "f"(lo));
    return r;
}

#define LDMATRIX_X4(r0, r1, r2, r3, addr) \
    asm volatile("ldmatrix.sync.aligned.m8n8.x4.shared.b16 {%0,%1,%2,%3}, [%4];" \
        : "=r"(r0), "=r"(r1), "=r"(r2), "=r"(r3) : "r"(addr))

// ------------------------------------------------------------------
// merged prep: blocks [0,1024) normalize codebook rows; blocks [1024,1536)
// transpose+normalize token tiles. One launch, both halves run concurrently.
__global__ void prep_kernel(const float* __restrict__ cb,
                            const float* __restrict__ x) {
    int tid = threadIdx.x, wid = tid >> 5, lane = tid & 31;
    if (blockIdx.x < 1024) {
        if (blockIdx.x == 0 && tid == 0) g_acc = 0.0;
        int row = blockIdx.x * 8 + wid;
        const float4* src = (const float4*)(cb + (size_t)row * DD);
        float4 v0 = src[lane];
        float4 v1 = src[lane + 32];
        float ss = v0.x*v0.x + v0.y*v0.y + v0.z*v0.z + v0.w*v0.w
                 + v1.x*v1.x + v1.y*v1.y + v1.z*v1.z + v1.w*v1.w;
        #pragma unroll
        for (int o = 16; o; o >>= 1) ss += __shfl_xor_sync(~0u, ss, o);
        float inv = 1.0f / fmaxf(sqrtf(ss), EPSF);
        v0.x*=inv; v0.y*=inv; v0.z*=inv; v0.w*=inv;
        v1.x*=inv; v1.y*=inv; v1.z*=inv; v1.w*=inv;
        float4* dst = (float4*)(g_cbn + (size_t)row * DD);
        dst[lane] = v0; dst[lane + 32] = v1;
        uint32_t u0 = (uint32_t)pack_e4m3x2(v0.x*F8SCALE, v0.y*F8SCALE)
                    | ((uint32_t)pack_e4m3x2(v0.z*F8SCALE, v0.w*F8SCALE) << 16);
        uint32_t u1 = (uint32_t)pack_e4m3x2(v1.x*F8SCALE, v1.y*F8SCALE)
                    | ((uint32_t)pack_e4m3x2(v1.z*F8SCALE, v1.w*F8SCALE) << 16);
        uint32_t* h8 = (uint32_t*)(g_c8 + (size_t)row * DD);
        h8[lane] = u0; h8[lane + 32] = u1;
    } else {
        __shared__ float tile[32][261];
        int q = blockIdx.x - 1024;          // 0..511
        int b = q >> 7, l0 = (q & 127) * 32;
        #pragma unroll
        for (int j = 0; j < 32; j++) {
            int d = wid * 32 + j;
            tile[lane][d] = x[(size_t)b * DD * LL + (size_t)d * LL + l0 + lane];
        }
        __syncthreads();
        #pragma unroll
        for (int i = 0; i < 4; i++) {
            int t = wid * 4 + i;
            int n = b * LL + l0 + t;
            float ss = 0.0f;
            #pragma unroll
            for (int j = 0; j < 8; j++) { float v = tile[t][lane + 32*j]; ss = fmaf(v, v, ss); }
            #pragma unroll
            for (int o = 16; o; o >>= 1) ss += __shfl_xor_sync(~0u, ss, o);
            float nrm = fmaxf(sqrtf(ss), EPSF);
            float inv = 1.0f / nrm;
            if (lane == 0) g_norm[n] = nrm;
            #pragma unroll
            for (int j = 0; j < 8; j++) {
                int d = lane + 32*j;
                float v = tile[t][d] * inv;
                g_xn[(size_t)n * DD + d] = v;
                g_x8[(size_t)n * DD + d] = (uint8_t)(pack_e4m3x2(v*F8SCALE, 0.0f) & 0xFF);
            }
        }
    }
}

// ------------------------------------------------------------------
#define CP_ASYNC16(dst, src) \
    asm volatile("cp.async.cg.shared.global [%0], [%1], 16;\n" :: "r"(dst), "l"(src))

// A: both k-halves, loaded once (8 cp.async per thread)
__device__ __forceinline__ void load_A(uint32_t sb, int mbase, int tid) {
    #pragma unroll
    for (int h = 0; h < 2; h++)
        #pragma unroll
        for (int i = 0; i < 4; i++) {
            int idx = tid + i * 256;
            int row = idx >> 3, c = (idx & 7) * 16;
            CP_ASYNC16(sb + h * STAGE + row * SLK + c,
                       g_x8 + (size_t)(mbase + row) * DD + h * 128 + c);
        }
}

// B stage s -> ring slot r (4 cp.async per thread)
__device__ __forceinline__ void load_B(int s, int r, uint32_t sb,
                                       int slice, int tid) {
    int kb = (s & 1) * 128;
    int kc = s >> 1;
    const uint8_t* src = g_c8 + (size_t)(slice * CPS + kc * BN) * DD + kb;
    uint32_t dst = sb + SB_OFF + r * STAGE;
    #pragma unroll
    for (int i = 0; i < 4; i++) {
        int idx = tid + i * 256;
        int row = idx >> 3, c = (idx & 7) * 16;
        CP_ASYNC16(dst + row * SLK + c, src + (size_t)row * DD + c);
    }
}

// fused fp8 mma GEMM + per-(token,slice) packed top-3; ldmatrix feed.
// A resident in smem; B 3-slot ring. grid = (KSPLIT, NN/BM).
// (mainloop identical to the round-9/11/12 best — at the mma.sync floor)
__global__ void __launch_bounds__(256, 2) gemm_topk_kernel() {
    extern __shared__ uint8_t sm[];
    uint32_t sb = (uint32_t)__cvta_generic_to_shared(sm);
    int tid = threadIdx.x;
    int wid = tid >> 5, lane = tid & 31;
    int warp_m = wid & 3, warp_n = wid >> 2;     // 4x2 warps: 32 rows x 64 cols
    int grp = lane >> 2, qid = lane & 3;
    int slice = blockIdx.x;
    int mbase = blockIdx.y * BM;

    int lt = lane >> 3, lr = lane & 7;
    uint32_t offA[2];
    #pragma unroll
    for (int mi = 0; mi < 2; mi++)
        offA[mi] = (uint32_t)((warp_m*32 + mi*16 + (lt & 1)*8 + lr) * SLK + (lt >> 1) * 16);
    uint32_t offB[4];
    #pragma unroll
    for (int p = 0; p < 4; p++)
        offB[p] = (uint32_t)((warp_n*64 + (2*p + (lt >> 1))*8 + lr) * SLK + (lt & 1) * 16);

    load_A(sb, mbase, tid);
    load_B(0, 0, sb, slice, tid);
    asm volatile("cp.async.commit_group;\n" ::);
    load_B(1, 1, sb, slice, tid);
    asm volatile("cp.async.commit_group;\n" ::);

    uint32_t t1[4], t2[4], t3[4];
    #pragma unroll
    for (int s4 = 0; s4 < 4; s4++) { t1[s4]=0; t2[s4]=0; t3[s4]=0; }

    float c[2][8][4];

    #pragma unroll 1
    for (int s = 0; s < NSTAGES; s++) {
        if ((s & 1) == 0) {
            #pragma unroll
            for (int mi = 0; mi < 2; mi++)
                #pragma unroll
                for (int ni = 0; ni < 8; ni++)
                    #pragma unroll
                    for (int j = 0; j < 4; j++) c[mi][ni][j] = 0.0f;
        }
        if (s < NSTAGES - 2) asm volatile("cp.async.wait_group 1;\n" ::);
        else                 asm volatile("cp.async.wait_group 0;\n" ::);
        __syncthreads();
        if (s + 2 < NSTAGES) {
            load_B(s + 2, (s + 2) % 3, sb, slice, tid);
            asm volatile("cp.async.commit_group;\n" ::);
        }

        uint32_t a_base = sb + (uint32_t)(s & 1) * STAGE;
        uint32_t b_base = sb + SB_OFF + (uint32_t)(s % 3) * STAGE;
        #pragma unroll
        for (int ks = 0; ks < 4; ks++) {
            uint32_t ksb = ks * 32;
            uint32_t a[2][4], b[8][2];
            #pragma unroll
            for (int mi = 0; mi < 2; mi++)
                LDMATRIX_X4(a[mi][0], a[mi][1], a[mi][2], a[mi][3],
                            a_base + offA[mi] + ksb);
            #pragma unroll
            for (int p = 0; p < 4; p++)
                LDMATRIX_X4(b[2*p][0], b[2*p][1], b[2*p+1][0], b[2*p+1][1],
                            b_base + offB[p] + ksb);
            #pragma unroll
            for (int mi = 0; mi < 2; mi++)
                #pragma unroll
                for (int ni = 0; ni < 8; ni++)
                    asm volatile(
                        "mma.sync.aligned.m16n8k32.row.col.f32.e4m3.e4m3.f32 "
                        "{%0,%1,%2,%3}, {%4,%5,%6,%7}, {%8,%9}, {%0,%1,%2,%3};\n"
                        : "+f"(c[mi][ni][0]), "+f"(c[mi][ni][1]),
                          "+f"(c[mi][ni][2]), "+f"(c[mi][ni][3])
                        : "r"(a[mi][0]), "r"(a[mi][1]), "r"(a[mi][2]), "r"(a[mi][3]),
                          "r"(b[ni][0]), "r"(b[ni][1]));
        }

        if (s & 1) {   // chunk kc = s>>1 complete: update packed top-3
            int kc = s >> 1;
            #pragma unroll
            for (int s4 = 0; s4 < 4; s4++) {
                int mi = s4 >> 1, h = s4 & 1;
                float m0 = -1e30f;
                #pragma unroll
                for (int ni = 0; ni < 8; ni++)
                    m0 = fmaxf(m0, fmaxf(c[mi][ni][h*2], c[mi][ni][h*2+1]));
                if ((__float_as_uint(m0 + 512.0f) | 0x1FFu) >= t3[s4]) {
                    #pragma unroll
                    for (int ni = 0; ni < 8; ni++)
                        #pragma unroll
                        for (int j = 0; j < 2; j++) {
                            float v = c[mi][ni][h*2 + j];
                            uint32_t col = kc*128 + warp_n*64 + ni*8 + qid*2 + j;
                            uint32_t u = (__float_as_uint(v + 512.0f) & 0xFFFFFE00u)
                                       | (511u - col);
                            if (u > t1[s4])      { t3[s4]=t2[s4]; t2[s4]=t1[s4]; t1[s4]=u; }
                            else if (u > t2[s4]) { t3[s4]=t2[s4]; t2[s4]=u; }
                            else if (u > t3[s4]) { t3[s4]=u; }
                        }
                }
            }
        }
    }

    __syncthreads();
    uint32_t* mk = (uint32_t*)sm;      // [128][24]
    #pragma unroll
    for (int s4 = 0; s4 < 4; s4++) {
        int row = warp_m*32 + (s4>>1)*16 + (s4&1)*8 + grp;
        int base2 = row * 24 + (warp_n*4 + qid) * 3;
        mk[base2+0] = t1[s4]; mk[base2+1] = t2[s4]; mk[base2+2] = t3[s4];
    }
    __syncthreads();
    if (tid < 128) {
        uint32_t b1=0, b2=0, b3=0;
        #pragma unroll
        for (int s2 = 0; s2 < 24; s2++) {
            uint32_t u = mk[tid*24 + s2];
            if (u > b1)      { b3=b2; b2=b1; b1=u; }
            else if (u > b2) { b3=b2; b2=u; }
            else if (u > b3) { b3=u; }
        }
        int n = mbase + tid;
        int base2 = n * NCAND + slice * 3;
        uint32_t ks_[3] = {b1, b2, b3};
        #pragma unroll
        for (int j = 0; j < 3; j++) {
            uint32_t u = ks_[j];
            g_candv[base2+j] = (__uint_as_float(u & 0xFFFFFE00u) - 512.0f) * (1.0f/256.0f);
            g_candi[base2+j] = slice * CPS + (int)(511u - (u & 0x1FFu));
        }
    }
}

// ------------------------------------------------------------------
// fused: ballot-prefiltered margin rescue (single-survivor fast path +
// 2-wide pipelined exact fp32 rescore) -> rotation -> commit loss ->
// transposed write -> last-block loss tail.
// 1024 threads: ONE warp per token (32 tokens per block).
// (rescue/rotation body identical to the round-12 best)
__global__ void __launch_bounds__(1024) rotate_out_kernel(float* __restrict__ out,
                                                          int out_size) {
    __shared__ float tile[256][33];
    int b = blockIdx.y, l0 = blockIdx.x * 32;
    int tid = threadIdx.x, wid = tid >> 5, lane = tid & 31;

    int t = wid;                       // token slot within the 32-token tile
    int n = b * LL + l0 + t;

    // hoist x loads to overlap with candidate phase
    const float4* xp = (const float4*)(g_xn + (size_t)n * DD);
    float4 x0 = xp[lane], x1 = xp[lane + 32];

    float va = g_candv[n*NCAND + lane];
    int   ka = g_candi[n*NCAND + lane];
    float vb = (lane < 16) ? g_candv[n*NCAND + 32 + lane] : -3.0f;
    int   kb = (lane < 16) ? g_candi[n*NCAND + 32 + lane] : 0x7fffffff;
    float rmax = fmaxf(va, vb);
    #pragma unroll
    for (int o = 16; o; o >>= 1) rmax = fmaxf(rmax, __shfl_xor_sync(~0u, rmax, o));
    float thr = rmax - MARGIN;

    unsigned m1 = __ballot_sync(~0u, va >= thr);
    unsigned m2 = __ballot_sync(~0u, vb >= thr);   // lanes >=16 hold -3 -> never pass

    float bestv = -3.0f; int besti = 0x7fffffff;
    if (__popc(m1) + __popc(m2) == 1) {
        // single survivor: margin guarantees it is the exact argmax
        int src = m1 ? (__ffs(m1) - 1) : (__ffs(m2) - 1);
        besti = m1 ? __shfl_sync(~0u, ka, src) : __shfl_sync(~0u, kb, src);
    } else {
        float4 xa0 = xp[lane*2], xa1 = xp[lane*2 + 1];
        while (m1 | m2) {
            // pull up to TWO candidates; their gathers overlap (MLP=2)
            int k0, k1 = -1;
            if (m1) { int ci = __ffs(m1) - 1; m1 &= m1 - 1; k0 = __shfl_sync(~0u, ka, ci); }
            else    { int ci = __ffs(m2) - 1; m2 &= m2 - 1; k0 = __shfl_sync(~0u, kb, ci); }
            if (m1)      { int ci = __ffs(m1) - 1; m1 &= m1 - 1; k1 = __shfl_sync(~0u, ka, ci); }
            else if (m2) { int ci = __ffs(m2) - 1; m2 &= m2 - 1; k1 = __shfl_sync(~0u, kb, ci); }

            const float4* cp0 = (const float4*)(g_cbn + (size_t)k0 * DD);
            float4 c00 = cp0[lane*2], c01 = cp0[lane*2 + 1];
            float d0 = xa0.x*c00.x + xa0.y*c00.y + xa0.z*c00.z + xa0.w*c00.w
                     + xa1.x*c01.x + xa1.y*c01.y + xa1.z*c01.z + xa1.w*c01.w;
            float d1 = -3.0f;
            if (k1 >= 0) {
                const float4* cp1 = (const float4*)(g_cbn + (size_t)k1 * DD);
                float4 c10 = cp1[lane*2], c11 = cp1[lane*2 + 1];
                d1 = xa0.x*c10.x + xa0.y*c10.y + xa0.z*c10.z + xa0.w*c10.w
                   + xa1.x*c11.x + xa1.y*c11.y + xa1.z*c11.z + xa1.w*c11.w;
            }
            #pragma unroll
            for (int o = 16; o; o >>= 1) {
                d0 += __shfl_xor_sync(~0u, d0, o);
                d1 += __shfl_xor_sync(~0u, d1, o);
            }
            if (d0 > bestv || (d0 == bestv && k0 < besti)) { bestv = d0; besti = k0; }
            if (k1 >= 0 && (d1 > bestv || (d1 == bestv && k1 < besti))) { bestv = d1; besti = k1; }
        }
    }

    float nrm = g_norm[n];
    const float4* qp = (const float4*)(g_cbn + (size_t)besti * DD);
    float4 q0 = qp[lane], q1 = qp[lane + 32];
    float s0x = x0.x + q0.x, s0y = x0.y + q0.y, s0z = x0.z + q0.z, s0w = x0.w + q0.w;
    float s1x = x1.x + q1.x, s1y = x1.y + q1.y, s1z = x1.z + q1.z, s1w = x1.w + q1.w;
    float ss = s0x*s0x + s0y*s0y + s0z*s0z + s0w*s0w
             + s1x*s1x + s1y*s1y + s1z*s1z + s1w*s1w;
    float xs = x0.x*s0x + x0.y*s0y + x0.z*s0z + x0.w*s0w
             + x1.x*s1x + x1.y*s1y + x1.z*s1z + x1.w*s1w;
    #pragma unroll
    for (int o = 16; o; o >>= 1) {
        ss += __shfl_xor_sync(~0u, ss, o);
        xs += __shfl_xor_sync(~0u, xs, o);
    }
    float sn = fmaxf(sqrtf(ss), EPSF);
    float cc = 2.0f * (xs / sn) / sn;

    float4 r0, r1;
    r0.x = x0.x - cc*s0x + 2.0f*q0.x;  r0.y = x0.y - cc*s0y + 2.0f*q0.y;
    r0.z = x0.z - cc*s0z + 2.0f*q0.z;  r0.w = x0.w - cc*s0w + 2.0f*q0.w;
    r1.x = x1.x - cc*s1x + 2.0f*q1.x;  r1.y = x1.y - cc*s1y + 2.0f*q1.y;
    r1.z = x1.z - cc*s1z + 2.0f*q1.z;  r1.w = x1.w - cc*s1w + 2.0f*q1.w;

    int d0i = lane * 4;
    tile[d0i+0][t] = r0.x; tile[d0i+1][t] = r0.y; tile[d0i+2][t] = r0.z; tile[d0i+3][t] = r0.w;
    tile[128+d0i+0][t] = r1.x; tile[128+d0i+1][t] = r1.y;
    tile[128+d0i+2][t] = r1.z; tile[128+d0i+3][t] = r1.w;

    float e0x = r0.x - x0.x*nrm, e0y = r0.y - x0.y*nrm, e0z = r0.z - x0.z*nrm, e0w = r0.w - x0.w*nrm;
    float e1x = r1.x - x1.x*nrm, e1y = r1.y - x1.y*nrm, e1z = r1.z - x1.z*nrm, e1w = r1.w - x1.w*nrm;
    float cs = e0x*e0x + e0y*e0y + e0z*e0z + e0w*e0w
             + e1x*e1x + e1y*e1y + e1z*e1z + e1w*e1w;
    #pragma unroll
    for (int o = 16; o; o >>= 1) cs += __shfl_xor_sync(~0u, cs, o);
    if (lane == 0) atomicAdd(&g_acc, (double)cs);

    __syncthreads();

    // coalesced transposed write: warp w writes d rows [w*8, w*8+8)
    #pragma unroll
    for (int j = 0; j < 8; j++) {
        int d = wid * 8 + j;
        out[(size_t)b * DD * LL + (size_t)d * LL + l0 + lane] = tile[d][lane];
    }

    // last block writes the loss tail (graph-replay safe: counter resets)
    if (tid == 0) {
        __threadfence();
        unsigned old = atomicAdd(&g_done, 1u);
        if (old == 511u) {
            g_done = 0;
            __threadfence();
            long q = (long)BB * DD * LL;
            float loss = (float)(0.25 * g_acc / (double)((long)NN * DD));
            for (long i = q; i < (long)out_size; i++) out[i] = loss;
        }
    }
}

// ------------------------------------------------------------------
extern "C" void kernel_launch(void* const* d_in, const int* in_sizes, int n_in,
                              void* d_out, int out_size) {
    const float* x  = (const float*)d_in[0];   // [4,256,4096]
    const float* cb = (const float*)d_in[1];   // [8192,256]
    float* out = (float*)d_out;

    static int attr_set = 0;
    if (!attr_set) {
        cudaFuncSetAttribute(gemm_topk_kernel,
                             cudaFuncAttributeMaxDynamicSharedMemorySize, GSMEM);
        attr_set = 1;
    }

    prep_kernel<<<1536, 256>>>(cb, x);
    gemm_topk_kernel<<<dim3(KSPLIT, NN / BM), 256, GSMEM>>>();
    rotate_out_kernel<<<dim3(LL / 32, BB), 1024>>>(out, out_size);
}

// round 16
// speedup vs baseline: 1.0167x; 1.0145x over previous
#include <cuda_runtime.h>
#include <cuda_bf16.h>
#include <math.h>
#include <stdint.h>

#define BB 4
#define DD 256
#define LL 4096
#define NN (BB*LL)      // 16384 tokens
#define KK 8192
#define EPSF 1e-12f
#define MARGIN 0.03f          // fp8 rescue margin (unscaled sims)
#define F8SCALE 16.0f         // per-side scale -> dots scaled by 256

#define KSPLIT 16
#define CPS (KK/KSPLIT)        // 512 codes per slice
#define NCAND (KSPLIT*3)       // 48 candidates per token

// ---- GEMM tiling ----
#define BM 128
#define BN 128
#define SLK 144                 // smem row stride bytes (conflict-free)
#define STAGE 18432             // 128 rows x 144 B (one operand, one k-half)
#define SA_BYTES (2*STAGE)      // A resident: both k-halves
#define SB_OFF SA_BYTES         // B ring base
#define NSTAGES 8               // 4 chunks x 2 k-halves
#define GSMEM (SA_BYTES + 3*STAGE)   // 92160

// ---- device scratch ----
__device__ float    g_cbn[KK*DD];     // normalized codebook fp32 (8 MB)
__device__ float    g_xn[NN*DD];      // normalized tokens fp32 (16 MB)
__device__ uint8_t  g_c8[KK*DD];      // fp8 e4m3 codebook *16 (2 MB)
__device__ uint8_t  g_x8[NN*DD];      // fp8 e4m3 tokens *16 (4 MB)
__device__ float    g_norm[NN];
__device__ float    g_candv[NN*NCAND];
__device__ int      g_candi[NN*NCAND];
__device__ double   g_acc;

// ------------------------------------------------------------------
// result: low byte = e4m3(lo), high byte = e4m3(hi)
__device__ __forceinline__ uint16_t pack_e4m3x2(float lo, float hi) {
    uint16_t r;
    asm("cvt.rn.satfinite.e4m3x2.f32 %0, %1, %2;" : "=h"(r) : "f"(hi), "f"(lo));
    return r;
}

#define LDMATRIX_X4(r0, r1, r2, r3, addr) \
    asm volatile("ldmatrix.sync.aligned.m8n8.x4.shared.b16 {%0,%1,%2,%3}, [%4];" \
        : "=r"(r0), "=r"(r1), "=r"(r2), "=r"(r3) : "r"(addr))

// ------------------------------------------------------------------
// merged prep: blocks [0,1024) normalize codebook rows; blocks [1024,1536)
// transpose+normalize token tiles. One launch, both halves run concurrently.
__global__ void prep_kernel(const float* __restrict__ cb,
                            const float* __restrict__ x) {
    int tid = threadIdx.x, wid = tid >> 5, lane = tid & 31;
    if (blockIdx.x < 1024) {
        if (blockIdx.x == 0 && tid == 0) g_acc = 0.0;
        int row = blockIdx.x * 8 + wid;
        const float4* src = (const float4*)(cb + (size_t)row * DD);
        float4 v0 = src[lane];
        float4 v1 = src[lane + 32];
        float ss = v0.x*v0.x + v0.y*v0.y + v0.z*v0.z + v0.w*v0.w
                 + v1.x*v1.x + v1.y*v1.y + v1.z*v1.z + v1.w*v1.w;
        #pragma unroll
        for (int o = 16; o; o >>= 1) ss += __shfl_xor_sync(~0u, ss, o);
        float inv = 1.0f / fmaxf(sqrtf(ss), EPSF);
        v0.x*=inv; v0.y*=inv; v0.z*=inv; v0.w*=inv;
        v1.x*=inv; v1.y*=inv; v1.z*=inv; v1.w*=inv;
        float4* dst = (float4*)(g_cbn + (size_t)row * DD);
        dst[lane] = v0; dst[lane + 32] = v1;
        uint32_t u0 = (uint32_t)pack_e4m3x2(v0.x*F8SCALE, v0.y*F8SCALE)
                    | ((uint32_t)pack_e4m3x2(v0.z*F8SCALE, v0.w*F8SCALE) << 16);
        uint32_t u1 = (uint32_t)pack_e4m3x2(v1.x*F8SCALE, v1.y*F8SCALE)
                    | ((uint32_t)pack_e4m3x2(v1.z*F8SCALE, v1.w*F8SCALE) << 16);
        uint32_t* h8 = (uint32_t*)(g_c8 + (size_t)row * DD);
        h8[lane] = u0; h8[lane + 32] = u1;
    } else {
        __shared__ float tile[32][261];
        int q = blockIdx.x - 1024;          // 0..511
        int b = q >> 7, l0 = (q & 127) * 32;
        #pragma unroll
        for (int j = 0; j < 32; j++) {
            int d = wid * 32 + j;
            tile[lane][d] = x[(size_t)b * DD * LL + (size_t)d * LL + l0 + lane];
        }
        __syncthreads();
        #pragma unroll
        for (int i = 0; i < 4; i++) {
            int t = wid * 4 + i;
            int n = b * LL + l0 + t;
            float ss = 0.0f;
            #pragma unroll
            for (int j = 0; j < 8; j++) { float v = tile[t][lane + 32*j]; ss = fmaf(v, v, ss); }
            #pragma unroll
            for (int o = 16; o; o >>= 1) ss += __shfl_xor_sync(~0u, ss, o);
            float nrm = fmaxf(sqrtf(ss), EPSF);
            float inv = 1.0f / nrm;
            if (lane == 0) g_norm[n] = nrm;
            #pragma unroll
            for (int j = 0; j < 8; j++) {
                int d = lane + 32*j;
                float v = tile[t][d] * inv;
                g_xn[(size_t)n * DD + d] = v;
                g_x8[(size_t)n * DD + d] = (uint8_t)(pack_e4m3x2(v*F8SCALE, 0.0f) & 0xFF);
            }
        }
    }
}

// ------------------------------------------------------------------
#define CP_ASYNC16(dst, src) \
    asm volatile("cp.async.cg.shared.global [%0], [%1], 16;\n" :: "r"(dst), "l"(src))

// A: both k-halves, loaded once (8 cp.async per thread)
__device__ __forceinline__ void load_A(uint32_t sb, int mbase, int tid) {
    #pragma unroll
    for (int h = 0; h < 2; h++)
        #pragma unroll
        for (int i = 0; i < 4; i++) {
            int idx = tid + i * 256;
            int row = idx >> 3, c = (idx & 7) * 16;
            CP_ASYNC16(sb + h * STAGE + row * SLK + c,
                       g_x8 + (size_t)(mbase + row) * DD + h * 128 + c);
        }
}

// B stage s -> ring slot r (4 cp.async per thread)
__device__ __forceinline__ void load_B(int s, int r, uint32_t sb,
                                       int slice, int tid) {
    int kb = (s & 1) * 128;
    int kc = s >> 1;
    const uint8_t* src = g_c8 + (size_t)(slice * CPS + kc * BN) * DD + kb;
    uint32_t dst = sb + SB_OFF + r * STAGE;
    #pragma unroll
    for (int i = 0; i < 4; i++) {
        int idx = tid + i * 256;
        int row = idx >> 3, c = (idx & 7) * 16;
        CP_ASYNC16(dst + row * SLK + c, src + (size_t)row * DD + c);
    }
}

// fused fp8 mma GEMM + per-(token,slice) packed top-3; ldmatrix feed.
// A resident in smem; B 3-slot ring. grid = (KSPLIT, NN/BM).
// (mainloop identical to the round-9/11/12 best — at the mma.sync floor)
__global__ void __launch_bounds__(256, 2) gemm_topk_kernel() {
    extern __shared__ uint8_t sm[];
    uint32_t sb = (uint32_t)__cvta_generic_to_shared(sm);
    int tid = threadIdx.x;
    int wid = tid >> 5, lane = tid & 31;
    int warp_m = wid & 3, warp_n = wid >> 2;     // 4x2 warps: 32 rows x 64 cols
    int grp = lane >> 2, qid = lane & 3;
    int slice = blockIdx.x;
    int mbase = blockIdx.y * BM;

    int lt = lane >> 3, lr = lane & 7;
    uint32_t offA[2];
    #pragma unroll
    for (int mi = 0; mi < 2; mi++)
        offA[mi] = (uint32_t)((warp_m*32 + mi*16 + (lt & 1)*8 + lr) * SLK + (lt >> 1) * 16);
    uint32_t offB[4];
    #pragma unroll
    for (int p = 0; p < 4; p++)
        offB[p] = (uint32_t)((warp_n*64 + (2*p + (lt >> 1))*8 + lr) * SLK + (lt & 1) * 16);

    load_A(sb, mbase, tid);
    load_B(0, 0, sb, slice, tid);
    asm volatile("cp.async.commit_group;\n" ::);
    load_B(1, 1, sb, slice, tid);
    asm volatile("cp.async.commit_group;\n" ::);

    uint32_t t1[4], t2[4], t3[4];
    #pragma unroll
    for (int s4 = 0; s4 < 4; s4++) { t1[s4]=0; t2[s4]=0; t3[s4]=0; }

    float c[2][8][4];

    #pragma unroll 1
    for (int s = 0; s < NSTAGES; s++) {
        if ((s & 1) == 0) {
            #pragma unroll
            for (int mi = 0; mi < 2; mi++)
                #pragma unroll
                for (int ni = 0; ni < 8; ni++)
                    #pragma unroll
                    for (int j = 0; j < 4; j++) c[mi][ni][j] = 0.0f;
        }
        if (s < NSTAGES - 2) asm volatile("cp.async.wait_group 1;\n" ::);
        else                 asm volatile("cp.async.wait_group 0;\n" ::);
        __syncthreads();
        if (s + 2 < NSTAGES) {
            load_B(s + 2, (s + 2) % 3, sb, slice, tid);
            asm volatile("cp.async.commit_group;\n" ::);
        }

        uint32_t a_base = sb + (uint32_t)(s & 1) * STAGE;
        uint32_t b_base = sb + SB_OFF + (uint32_t)(s % 3) * STAGE;
        #pragma unroll
        for (int ks = 0; ks < 4; ks++) {
            uint32_t ksb = ks * 32;
            uint32_t a[2][4], b[8][2];
            #pragma unroll
            for (int mi = 0; mi < 2; mi++)
                LDMATRIX_X4(a[mi][0], a[mi][1], a[mi][2], a[mi][3],
                            a_base + offA[mi] + ksb);
            #pragma unroll
            for (int p = 0; p < 4; p++)
                LDMATRIX_X4(b[2*p][0], b[2*p][1], b[2*p+1][0], b[2*p+1][1],
                            b_base + offB[p] + ksb);
            #pragma unroll
            for (int mi = 0; mi < 2; mi++)
                #pragma unroll
                for (int ni = 0; ni < 8; ni++)
                    asm volatile(
                        "mma.sync.aligned.m16n8k32.row.col.f32.e4m3.e4m3.f32 "
                        "{%0,%1,%2,%3}, {%4,%5,%6,%7}, {%8,%9}, {%0,%1,%2,%3};\n"
                        : "+f"(c[mi][ni][0]), "+f"(c[mi][ni][1]),
                          "+f"(c[mi][ni][2]), "+f"(c[mi][ni][3])
                        : "r"(a[mi][0]), "r"(a[mi][1]), "r"(a[mi][2]), "r"(a[mi][3]),
                          "r"(b[ni][0]), "r"(b[ni][1]));
        }

        if (s & 1) {   // chunk kc = s>>1 complete: update packed top-3
            int kc = s >> 1;
            #pragma unroll
            for (int s4 = 0; s4 < 4; s4++) {
                int mi = s4 >> 1, h = s4 & 1;
                float m0 = -1e30f;
                #pragma unroll
                for (int ni = 0; ni < 8; ni++)
                    m0 = fmaxf(m0, fmaxf(c[mi][ni][h*2], c[mi][ni][h*2+1]));
                if ((__float_as_uint(m0 + 512.0f) | 0x1FFu) >= t3[s4]) {
                    #pragma unroll
                    for (int ni = 0; ni < 8; ni++)
                        #pragma unroll
                        for (int j = 0; j < 2; j++) {
                            float v = c[mi][ni][h*2 + j];
                            uint32_t col = kc*128 + warp_n*64 + ni*8 + qid*2 + j;
                            uint32_t u = (__float_as_uint(v + 512.0f) & 0xFFFFFE00u)
                                       | (511u - col);
                            if (u > t1[s4])      { t3[s4]=t2[s4]; t2[s4]=t1[s4]; t1[s4]=u; }
                            else if (u > t2[s4]) { t3[s4]=t2[s4]; t2[s4]=u; }
                            else if (u > t3[s4]) { t3[s4]=u; }
                        }
                }
            }
        }
    }

    __syncthreads();
    uint32_t* mk = (uint32_t*)sm;      // [128][24]
    #pragma unroll
    for (int s4 = 0; s4 < 4; s4++) {
        int row = warp_m*32 + (s4>>1)*16 + (s4&1)*8 + grp;
        int base2 = row * 24 + (warp_n*4 + qid) * 3;
        mk[base2+0] = t1[s4]; mk[base2+1] = t2[s4]; mk[base2+2] = t3[s4];
    }
    __syncthreads();
    if (tid < 128) {
        uint32_t b1=0, b2=0, b3=0;
        #pragma unroll
        for (int s2 = 0; s2 < 24; s2++) {
            uint32_t u = mk[tid*24 + s2];
            if (u > b1)      { b3=b2; b2=b1; b1=u; }
            else if (u > b2) { b3=b2; b2=u; }
            else if (u > b3) { b3=u; }
        }
        int n = mbase + tid;
        int base2 = n * NCAND + slice * 3;
        uint32_t ks_[3] = {b1, b2, b3};
        #pragma unroll
        for (int j = 0; j < 3; j++) {
            uint32_t u = ks_[j];
            g_candv[base2+j] = (__uint_as_float(u & 0xFFFFFE00u) - 512.0f) * (1.0f/256.0f);
            g_candi[base2+j] = slice * CPS + (int)(511u - (u & 0x1FFu));
        }
    }
}

// ------------------------------------------------------------------
// fused: margin rescue with winner-guess q-row prefetch.
// The bf16-argmax candidate's code row is gathered BEFORE the rescue; the
// multi-survivor exact fp32 rescore (round-12 body) only re-gathers if it
// disagrees with the guess (rare). 1024 threads: one warp per token.
__global__ void __launch_bounds__(1024) rotate_out_kernel(float* __restrict__ out) {
    __shared__ float tile[256][33];
    int b = blockIdx.y, l0 = blockIdx.x * 32;
    int tid = threadIdx.x, wid = tid >> 5, lane = tid & 31;

    int t = wid;                       // token slot within the 32-token tile
    int n = b * LL + l0 + t;

    const float4* xp = (const float4*)(g_xn + (size_t)n * DD);
    float4 x0 = xp[lane], x1 = xp[lane + 32];

    float va = g_candv[n*NCAND + lane];
    int   ka = g_candi[n*NCAND + lane];
    float vb = (lane < 16) ? g_candv[n*NCAND + 32 + lane] : -3.0f;
    int   kb = (lane < 16) ? g_candi[n*NCAND + 32 + lane] : 0x7fffffff;
    float rmax = fmaxf(va, vb);
    #pragma unroll
    for (int o = 16; o; o >>= 1) rmax = fmaxf(rmax, __shfl_xor_sync(~0u, rmax, o));
    float thr = rmax - MARGIN;

    // winner guess: first candidate achieving the bf16 max; prefetch its row
    unsigned gm1 = __ballot_sync(~0u, va == rmax);
    unsigned gm2 = __ballot_sync(~0u, vb == rmax);
    int kg = gm1 ? __shfl_sync(~0u, ka, __ffs(gm1) - 1)
                 : __shfl_sync(~0u, kb, __ffs(gm2) - 1);
    const float4* qpg = (const float4*)(g_cbn + (size_t)kg * DD);
    float4 q0 = qpg[lane], q1 = qpg[lane + 32];   // overlaps rescue below

    unsigned m1 = __ballot_sync(~0u, va >= thr);
    unsigned m2 = __ballot_sync(~0u, vb >= thr);

    int besti = kg;
    if (__popc(m1) + __popc(m2) > 1) {
        // exact fp32 rescore of all survivors (round-12 2-wide pipeline)
        float4 xa0 = xp[lane*2], xa1 = xp[lane*2 + 1];
        float bestv = -3.0f; besti = 0x7fffffff;
        while (m1 | m2) {
            int k0, k1 = -1;
            if (m1) { int ci = __ffs(m1) - 1; m1 &= m1 - 1; k0 = __shfl_sync(~0u, ka, ci); }
            else    { int ci = __ffs(m2) - 1; m2 &= m2 - 1; k0 = __shfl_sync(~0u, kb, ci); }
            if (m1)      { int ci = __ffs(m1) - 1; m1 &= m1 - 1; k1 = __shfl_sync(~0u, ka, ci); }
            else if (m2) { int ci = __ffs(m2) - 1; m2 &= m2 - 1; k1 = __shfl_sync(~0u, kb, ci); }

            const float4* cp0 = (const float4*)(g_cbn + (size_t)k0 * DD);
            float4 c00 = cp0[lane*2], c01 = cp0[lane*2 + 1];
            float d0 = xa0.x*c00.x + xa0.y*c00.y + xa0.z*c00.z + xa0.w*c00.w
                     + xa1.x*c01.x + xa1.y*c01.y + xa1.z*c01.z + xa1.w*c01.w;
            float d1 = -3.0f;
            if (k1 >= 0) {
                const float4* cp1 = (const float4*)(g_cbn + (size_t)k1 * DD);
                float4 c10 = cp1[lane*2], c11 = cp1[lane*2 + 1];
                d1 = xa0.x*c10.x + xa0.y*c10.y + xa0.z*c10.z + xa0.w*c10.w
                   + xa1.x*c11.x + xa1.y*c11.y + xa1.z*c11.z + xa1.w*c11.w;
            }
            #pragma unroll
            for (int o = 16; o; o >>= 1) {
                d0 += __shfl_xor_sync(~0u, d0, o);
                d1 += __shfl_xor_sync(~0u, d1, o);
            }
            if (d0 > bestv || (d0 == bestv && k0 < besti)) { bestv = d0; besti = k0; }
            if (k1 >= 0 && (d1 > bestv || (d1 == bestv && k1 < besti))) { bestv = d1; besti = k1; }
        }
        if (besti != kg) {   // guess missed (rare): fetch the true winner's row
            const float4* qp = (const float4*)(g_cbn + (size_t)besti * DD);
            q0 = qp[lane]; q1 = qp[lane + 32];
        }
    }

    float nrm = g_norm[n];
    float s0x = x0.x + q0.x, s0y = x0.y + q0.y, s0z = x0.z + q0.z, s0w = x0.w + q0.w;
    float s1x = x1.x + q1.x, s1y = x1.y + q1.y, s1z = x1.z + q1.z, s1w = x1.w + q1.w;
    float ss = s0x*s0x + s0y*s0y + s0z*s0z + s0w*s0w
             + s1x*s1x + s1y*s1y + s1z*s1z + s1w*s1w;
    float xs = x0.x*s0x + x0.y*s0y + x0.z*s0z + x0.w*s0w
             + x1.x*s1x + x1.y*s1y + x1.z*s1z + x1.w*s1w;
    #pragma unroll
    for (int o = 16; o; o >>= 1) {
        ss += __shfl_xor_sync(~0u, ss, o);
        xs += __shfl_xor_sync(~0u, xs, o);
    }
    float sn = fmaxf(sqrtf(ss), EPSF);
    float cc = 2.0f * (xs / sn) / sn;

    float4 r0, r1;
    r0.x = x0.x - cc*s0x + 2.0f*q0.x;  r0.y = x0.y - cc*s0y + 2.0f*q0.y;
    r0.z = x0.z - cc*s0z + 2.0f*q0.z;  r0.w = x0.w - cc*s0w + 2.0f*q0.w;
    r1.x = x1.x - cc*s1x + 2.0f*q1.x;  r1.y = x1.y - cc*s1y + 2.0f*q1.y;
    r1.z = x1.z - cc*s1z + 2.0f*q1.z;  r1.w = x1.w - cc*s1w + 2.0f*q1.w;

    int d0i = lane * 4;
    tile[d0i+0][t] = r0.x; tile[d0i+1][t] = r0.y; tile[d0i+2][t] = r0.z; tile[d0i+3][t] = r0.w;
    tile[128+d0i+0][t] = r1.x; tile[128+d0i+1][t] = r1.y;
    tile[128+d0i+2][t] = r1.z; tile[128+d0i+3][t] = r1.w;

    float e0x = r0.x - x0.x*nrm, e0y = r0.y - x0.y*nrm, e0z = r0.z - x0.z*nrm, e0w = r0.w - x0.w*nrm;
    float e1x = r1.x - x1.x*nrm, e1y = r1.y - x1.y*nrm, e1z = r1.z - x1.z*nrm, e1w = r1.w - x1.w*nrm;
    float cs = e0x*e0x + e0y*e0y + e0z*e0z + e0w*e0w
             + e1x*e1x + e1y*e1y + e1z*e1z + e1w*e1w;
    #pragma unroll
    for (int o = 16; o; o >>= 1) cs += __shfl_xor_sync(~0u, cs, o);
    if (lane == 0) atomicAdd(&g_acc, (double)cs);

    __syncthreads();

    // coalesced transposed write: warp w writes d rows [w*8, w*8+8)
    #pragma unroll
    for (int j = 0; j < 8; j++) {
        int d = wid * 8 + j;
        out[(size_t)b * DD * LL + (size_t)d * LL + l0 + lane] = tile[d][lane];
    }
}

__global__ void finalize_kernel(float* __restrict__ out, int out_size) {
    long q = (long)BB * DD * LL;
    float loss = (float)(0.25 * g_acc / (double)((long)NN * DD));
    for (long i = q + threadIdx.x; i < (long)out_size; i += blockDim.x) out[i] = loss;
}

// ------------------------------------------------------------------
extern "C" void kernel_launch(void* const* d_in, const int* in_sizes, int n_in,
                              void* d_out, int out_size) {
    const float* x  = (const float*)d_in[0];   // [4,256,4096]
    const float* cb = (const float*)d_in[1];   // [8192,256]
    float* out = (float*)d_out;

    static int attr_set = 0;
    if (!attr_set) {
        cudaFuncSetAttribute(gemm_topk_kernel,
                             cudaFuncAttributeMaxDynamicSharedMemorySize, GSMEM);
        attr_set = 1;
    }

    prep_kernel<<<1536, 256>>>(cb, x);
    gemm_topk_kernel<<<dim3(KSPLIT, NN / BM), 256, GSMEM>>>();
    rotate_out_kernel<<<dim3(LL / 32, BB), 1024>>>(out);
    finalize_kernel<<<1, 256>>>(out, out_size);
}

// round 17
// speedup vs baseline: 1.0204x; 1.0036x over previous
#include <cuda_runtime.h>
#include <cuda_bf16.h>
#include <math.h>
#include <stdint.h>

#define BB 4
#define DD 256
#define LL 4096
#define NN (BB*LL)      // 16384 tokens
#define KK 8192
#define EPSF 1e-12f
#define MARGIN 0.03f          // fp8 rescue margin (unscaled sims)
#define F8SCALE 16.0f         // per-side scale -> dots scaled by 256

#define KSPLIT 16
#define CPS (KK/KSPLIT)        // 512 codes per slice
#define NCAND (KSPLIT*3)       // 48 candidates per token

// ---- GEMM tiling ----
#define BM 128
#define BN 128
#define SLK 144                 // smem row stride bytes (conflict-free)
#define STAGE 18432             // 128 rows x 144 B (one operand, one k-half)
#define SA_BYTES (2*STAGE)      // A resident: both k-halves
#define SB_OFF SA_BYTES         // B ring base
#define NSTAGES 8               // 4 chunks x 2 k-halves
#define GSMEM (SA_BYTES + 3*STAGE)   // 92160

// ---- device scratch ----
__device__ float    g_cbn[KK*DD];     // normalized codebook fp32 (8 MB)
__device__ float    g_xn[NN*DD];      // normalized tokens fp32 (16 MB)
__device__ uint8_t  g_c8[KK*DD];      // fp8 e4m3 codebook *16 (2 MB)
__device__ uint8_t  g_x8[NN*DD];      // fp8 e4m3 tokens *16 (4 MB)
__device__ float    g_norm[NN];
__device__ float    g_candv[NN*NCAND];
__device__ int      g_candi[NN*NCAND];
__device__ double   g_acc;

// ------------------------------------------------------------------
// result: low byte = e4m3(lo), high byte = e4m3(hi)
__device__ __forceinline__ uint16_t pack_e4m3x2(float lo, float hi) {
    uint16_t r;
    asm("cvt.rn.satfinite.e4m3x2.f32 %0, %1, %2;" : "=h"(r) : "f"(hi), "f"(lo));
    return r;
}

#define LDMATRIX_X4(r0, r1, r2, r3, addr) \
    asm volatile("ldmatrix.sync.aligned.m8n8.x4.shared.b16 {%0,%1,%2,%3}, [%4];" \
        : "=r"(r0), "=r"(r1), "=r"(r2), "=r"(r3) : "r"(addr))

// ------------------------------------------------------------------
// merged prep: blocks [0,1024) normalize codebook rows; blocks [1024,1536)
// transpose+normalize token tiles. One launch, both halves run concurrently.
__global__ void prep_kernel(const float* __restrict__ cb,
                            const float* __restrict__ x) {
    int tid = threadIdx.x, wid = tid >> 5, lane = tid & 31;
    if (blockIdx.x < 1024) {
        if (blockIdx.x == 0 && tid == 0) g_acc = 0.0;
        int row = blockIdx.x * 8 + wid;
        const float4* src = (const float4*)(cb + (size_t)row * DD);
        float4 v0 = src[lane];
        float4 v1 = src[lane + 32];
        float ss = v0.x*v0.x + v0.y*v0.y + v0.z*v0.z + v0.w*v0.w
                 + v1.x*v1.x + v1.y*v1.y + v1.z*v1.z + v1.w*v1.w;
        #pragma unroll
        for (int o = 16; o; o >>= 1) ss += __shfl_xor_sync(~0u, ss, o);
        float inv = 1.0f / fmaxf(sqrtf(ss), EPSF);
        v0.x*=inv; v0.y*=inv; v0.z*=inv; v0.w*=inv;
        v1.x*=inv; v1.y*=inv; v1.z*=inv; v1.w*=inv;
        float4* dst = (float4*)(g_cbn + (size_t)row * DD);
        dst[lane] = v0; dst[lane + 32] = v1;
        uint32_t u0 = (uint32_t)pack_e4m3x2(v0.x*F8SCALE, v0.y*F8SCALE)
                    | ((uint32_t)pack_e4m3x2(v0.z*F8SCALE, v0.w*F8SCALE) << 16);
        uint32_t u1 = (uint32_t)pack_e4m3x2(v1.x*F8SCALE, v1.y*F8SCALE)
                    | ((uint32_t)pack_e4m3x2(v1.z*F8SCALE, v1.w*F8SCALE) << 16);
        uint32_t* h8 = (uint32_t*)(g_c8 + (size_t)row * DD);
        h8[lane] = u0; h8[lane + 32] = u1;
    } else {
        __shared__ float tile[32][261];
        int q = blockIdx.x - 1024;          // 0..511
        int b = q >> 7, l0 = (q & 127) * 32;
        #pragma unroll
        for (int j = 0; j < 32; j++) {
            int d = wid * 32 + j;
            tile[lane][d] = x[(size_t)b * DD * LL + (size_t)d * LL + l0 + lane];
        }
        __syncthreads();
        #pragma unroll
        for (int i = 0; i < 4; i++) {
            int t = wid * 4 + i;
            int n = b * LL + l0 + t;
            float ss = 0.0f;
            #pragma unroll
            for (int j = 0; j < 8; j++) { float v = tile[t][lane + 32*j]; ss = fmaf(v, v, ss); }
            #pragma unroll
            for (int o = 16; o; o >>= 1) ss += __shfl_xor_sync(~0u, ss, o);
            float nrm = fmaxf(sqrtf(ss), EPSF);
            float inv = 1.0f / nrm;
            if (lane == 0) g_norm[n] = nrm;
            #pragma unroll
            for (int j = 0; j < 8; j++) {
                int d = lane + 32*j;
                float v = tile[t][d] * inv;
                g_xn[(size_t)n * DD + d] = v;
                g_x8[(size_t)n * DD + d] = (uint8_t)(pack_e4m3x2(v*F8SCALE, 0.0f) & 0xFF);
            }
        }
    }
}

// ------------------------------------------------------------------
#define CP_ASYNC16(dst, src) \
    asm volatile("cp.async.cg.shared.global [%0], [%1], 16;\n" :: "r"(dst), "l"(src))

// A: both k-halves, loaded once (8 cp.async per thread)
__device__ __forceinline__ void load_A(uint32_t sb, int mbase, int tid) {
    #pragma unroll
    for (int h = 0; h < 2; h++)
        #pragma unroll
        for (int i = 0; i < 4; i++) {
            int idx = tid + i * 256;
            int row = idx >> 3, c = (idx & 7) * 16;
            CP_ASYNC16(sb + h * STAGE + row * SLK + c,
                       g_x8 + (size_t)(mbase + row) * DD + h * 128 + c);
        }
}

// B stage s -> ring slot r (4 cp.async per thread)
__device__ __forceinline__ void load_B(int s, int r, uint32_t sb,
                                       int slice, int tid) {
    int kb = (s & 1) * 128;
    int kc = s >> 1;
    const uint8_t* src = g_c8 + (size_t)(slice * CPS + kc * BN) * DD + kb;
    uint32_t dst = sb + SB_OFF + r * STAGE;
    #pragma unroll
    for (int i = 0; i < 4; i++) {
        int idx = tid + i * 256;
        int row = idx >> 3, c = (idx & 7) * 16;
        CP_ASYNC16(dst + row * SLK + c, src + (size_t)row * DD + c);
    }
}

// fused fp8 mma GEMM + per-(token,slice) packed top-3; ldmatrix feed.
// A resident in smem; B 3-slot ring. grid = (KSPLIT, NN/BM).
// (mainloop identical to the round-9/11/12/16 best — at the mma.sync ceiling)
__global__ void __launch_bounds__(256, 2) gemm_topk_kernel() {
    extern __shared__ uint8_t sm[];
    uint32_t sb = (uint32_t)__cvta_generic_to_shared(sm);
    int tid = threadIdx.x;
    int wid = tid >> 5, lane = tid & 31;
    int warp_m = wid & 3, warp_n = wid >> 2;     // 4x2 warps: 32 rows x 64 cols
    int grp = lane >> 2, qid = lane & 3;
    int slice = blockIdx.x;
    int mbase = blockIdx.y * BM;

    int lt = lane >> 3, lr = lane & 7;
    uint32_t offA[2];
    #pragma unroll
    for (int mi = 0; mi < 2; mi++)
        offA[mi] = (uint32_t)((warp_m*32 + mi*16 + (lt & 1)*8 + lr) * SLK + (lt >> 1) * 16);
    uint32_t offB[4];
    #pragma unroll
    for (int p = 0; p < 4; p++)
        offB[p] = (uint32_t)((warp_n*64 + (2*p + (lt >> 1))*8 + lr) * SLK + (lt & 1) * 16);

    load_A(sb, mbase, tid);
    load_B(0, 0, sb, slice, tid);
    asm volatile("cp.async.commit_group;\n" ::);
    load_B(1, 1, sb, slice, tid);
    asm volatile("cp.async.commit_group;\n" ::);

    uint32_t t1[4], t2[4], t3[4];
    #pragma unroll
    for (int s4 = 0; s4 < 4; s4++) { t1[s4]=0; t2[s4]=0; t3[s4]=0; }

    float c[2][8][4];

    #pragma unroll 1
    for (int s = 0; s < NSTAGES; s++) {
        if ((s & 1) == 0) {
            #pragma unroll
            for (int mi = 0; mi < 2; mi++)
                #pragma unroll
                for (int ni = 0; ni < 8; ni++)
                    #pragma unroll
                    for (int j = 0; j < 4; j++) c[mi][ni][j] = 0.0f;
        }
        if (s < NSTAGES - 2) asm volatile("cp.async.wait_group 1;\n" ::);
        else                 asm volatile("cp.async.wait_group 0;\n" ::);
        __syncthreads();
        if (s + 2 < NSTAGES) {
            load_B(s + 2, (s + 2) % 3, sb, slice, tid);
            asm volatile("cp.async.commit_group;\n" ::);
        }

        uint32_t a_base = sb + (uint32_t)(s & 1) * STAGE;
        uint32_t b_base = sb + SB_OFF + (uint32_t)(s % 3) * STAGE;
        #pragma unroll
        for (int ks = 0; ks < 4; ks++) {
            uint32_t ksb = ks * 32;
            uint32_t a[2][4], b[8][2];
            #pragma unroll
            for (int mi = 0; mi < 2; mi++)
                LDMATRIX_X4(a[mi][0], a[mi][1], a[mi][2], a[mi][3],
                            a_base + offA[mi] + ksb);
            #pragma unroll
            for (int p = 0; p < 4; p++)
                LDMATRIX_X4(b[2*p][0], b[2*p][1], b[2*p+1][0], b[2*p+1][1],
                            b_base + offB[p] + ksb);
            #pragma unroll
            for (int mi = 0; mi < 2; mi++)
                #pragma unroll
                for (int ni = 0; ni < 8; ni++)
                    asm volatile(
                        "mma.sync.aligned.m16n8k32.row.col.f32.e4m3.e4m3.f32 "
                        "{%0,%1,%2,%3}, {%4,%5,%6,%7}, {%8,%9}, {%0,%1,%2,%3};\n"
                        : "+f"(c[mi][ni][0]), "+f"(c[mi][ni][1]),
                          "+f"(c[mi][ni][2]), "+f"(c[mi][ni][3])
                        : "r"(a[mi][0]), "r"(a[mi][1]), "r"(a[mi][2]), "r"(a[mi][3]),
                          "r"(b[ni][0]), "r"(b[ni][1]));
        }

        if (s & 1) {   // chunk kc = s>>1 complete: update packed top-3
            int kc = s >> 1;
            #pragma unroll
            for (int s4 = 0; s4 < 4; s4++) {
                int mi = s4 >> 1, h = s4 & 1;
                float m0 = -1e30f;
                #pragma unroll
                for (int ni = 0; ni < 8; ni++)
                    m0 = fmaxf(m0, fmaxf(c[mi][ni][h*2], c[mi][ni][h*2+1]));
                if ((__float_as_uint(m0 + 512.0f) | 0x1FFu) >= t3[s4]) {
                    #pragma unroll
                    for (int ni = 0; ni < 8; ni++)
                        #pragma unroll
                        for (int j = 0; j < 2; j++) {
                            float v = c[mi][ni][h*2 + j];
                            uint32_t col = kc*128 + warp_n*64 + ni*8 + qid*2 + j;
                            uint32_t u = (__float_as_uint(v + 512.0f) & 0xFFFFFE00u)
                                       | (511u - col);
                            if (u > t1[s4])      { t3[s4]=t2[s4]; t2[s4]=t1[s4]; t1[s4]=u; }
                            else if (u > t2[s4]) { t3[s4]=t2[s4]; t2[s4]=u; }
                            else if (u > t3[s4]) { t3[s4]=u; }
                        }
                }
            }
        }
    }

    __syncthreads();
    uint32_t* mk = (uint32_t*)sm;      // [128][24]
    #pragma unroll
    for (int s4 = 0; s4 < 4; s4++) {
        int row = warp_m*32 + (s4>>1)*16 + (s4&1)*8 + grp;
        int base2 = row * 24 + (warp_n*4 + qid) * 3;
        mk[base2+0] = t1[s4]; mk[base2+1] = t2[s4]; mk[base2+2] = t3[s4];
    }
    __syncthreads();
    if (tid < 128) {
        uint32_t b1=0, b2=0, b3=0;
        #pragma unroll
        for (int s2 = 0; s2 < 24; s2++) {
            uint32_t u = mk[tid*24 + s2];
            if (u > b1)      { b3=b2; b2=b1; b1=u; }
            else if (u > b2) { b3=b2; b2=u; }
            else if (u > b3) { b3=u; }
        }
        int n = mbase + tid;
        int base2 = n * NCAND + slice * 3;
        uint32_t ks_[3] = {b1, b2, b3};
        #pragma unroll
        for (int j = 0; j < 3; j++) {
            uint32_t u = ks_[j];
            g_candv[base2+j] = (__uint_as_float(u & 0xFFFFFE00u) - 512.0f) * (1.0f/256.0f);
            g_candi[base2+j] = slice * CPS + (int)(511u - (u & 0x1FFu));
        }
    }
}

// ------------------------------------------------------------------
// rotate_out, using the identity rot == q0 (Householder reflection of xn
// across (xn+q0)/|..| maps xn -> -q0; +2q0 gives q0; inv_norm cancels).
// So: output = winning normalized code row; commit term = |q0 - xn*nrm|^2.
// Winner-guess prefetch + exact fp32 rescore for multi-survivor tokens.
// 1024 threads: one warp per token.
__global__ void __launch_bounds__(1024) rotate_out_kernel(float* __restrict__ out) {
    __shared__ float tile[256][33];
    int b = blockIdx.y, l0 = blockIdx.x * 32;
    int tid = threadIdx.x, wid = tid >> 5, lane = tid & 31;

    int t = wid;                       // token slot within the 32-token tile
    int n = b * LL + l0 + t;

    const float4* xp = (const float4*)(g_xn + (size_t)n * DD);
    float4 x0 = xp[lane], x1 = xp[lane + 32];

    float va = g_candv[n*NCAND + lane];
    int   ka = g_candi[n*NCAND + lane];
    float vb = (lane < 16) ? g_candv[n*NCAND + 32 + lane] : -3.0f;
    int   kb = (lane < 16) ? g_candi[n*NCAND + 32 + lane] : 0x7fffffff;
    float rmax = fmaxf(va, vb);
    #pragma unroll
    for (int o = 16; o; o >>= 1) rmax = fmaxf(rmax, __shfl_xor_sync(~0u, rmax, o));
    float thr = rmax - MARGIN;

    // winner guess: first candidate achieving the bf16 max; prefetch its row
    unsigned gm1 = __ballot_sync(~0u, va == rmax);
    unsigned gm2 = __ballot_sync(~0u, vb == rmax);
    int kg = gm1 ? __shfl_sync(~0u, ka, __ffs(gm1) - 1)
                 : __shfl_sync(~0u, kb, __ffs(gm2) - 1);
    const float4* qpg = (const float4*)(g_cbn + (size_t)kg * DD);
    float4 q0 = qpg[lane], q1 = qpg[lane + 32];   // overlaps rescue below

    unsigned m1 = __ballot_sync(~0u, va >= thr);
    unsigned m2 = __ballot_sync(~0u, vb >= thr);

    int besti = kg;
    if (__popc(m1) + __popc(m2) > 1) {
        // exact fp32 rescore of all survivors (2-wide pipelined)
        float4 xa0 = xp[lane*2], xa1 = xp[lane*2 + 1];
        float bestv = -3.0f; besti = 0x7fffffff;
        while (m1 | m2) {
            int k0, k1 = -1;
            if (m1) { int ci = __ffs(m1) - 1; m1 &= m1 - 1; k0 = __shfl_sync(~0u, ka, ci); }
            else    { int ci = __ffs(m2) - 1; m2 &= m2 - 1; k0 = __shfl_sync(~0u, kb, ci); }
            if (m1)      { int ci = __ffs(m1) - 1; m1 &= m1 - 1; k1 = __shfl_sync(~0u, ka, ci); }
            else if (m2) { int ci = __ffs(m2) - 1; m2 &= m2 - 1; k1 = __shfl_sync(~0u, kb, ci); }

            const float4* cp0 = (const float4*)(g_cbn + (size_t)k0 * DD);
            float4 c00 = cp0[lane*2], c01 = cp0[lane*2 + 1];
            float d0 = xa0.x*c00.x + xa0.y*c00.y + xa0.z*c00.z + xa0.w*c00.w
                     + xa1.x*c01.x + xa1.y*c01.y + xa1.z*c01.z + xa1.w*c01.w;
            float d1 = -3.0f;
            if (k1 >= 0) {
                const float4* cp1 = (const float4*)(g_cbn + (size_t)k1 * DD);
                float4 c10 = cp1[lane*2], c11 = cp1[lane*2 + 1];
                d1 = xa0.x*c10.x + xa0.y*c10.y + xa0.z*c10.z + xa0.w*c10.w
                   + xa1.x*c11.x + xa1.y*c11.y + xa1.z*c11.z + xa1.w*c11.w;
            }
            #pragma unroll
            for (int o = 16; o; o >>= 1) {
                d0 += __shfl_xor_sync(~0u, d0, o);
                d1 += __shfl_xor_sync(~0u, d1, o);
            }
            if (d0 > bestv || (d0 == bestv && k0 < besti)) { bestv = d0; besti = k0; }
            if (k1 >= 0 && (d1 > bestv || (d1 == bestv && k1 < besti))) { bestv = d1; besti = k1; }
        }
        if (besti != kg) {   // guess missed (rare): fetch the true winner's row
            const float4* qp = (const float4*)(g_cbn + (size_t)besti * DD);
            q0 = qp[lane]; q1 = qp[lane + 32];
        }
    }

    // output = q0 (identity); commit term computed directly
    float nrm = g_norm[n];
    int d0i = lane * 4;
    tile[d0i+0][t] = q0.x; tile[d0i+1][t] = q0.y; tile[d0i+2][t] = q0.z; tile[d0i+3][t] = q0.w;
    tile[128+d0i+0][t] = q1.x; tile[128+d0i+1][t] = q1.y;
    tile[128+d0i+2][t] = q1.z; tile[128+d0i+3][t] = q1.w;

    float e0x = q0.x - x0.x*nrm, e0y = q0.y - x0.y*nrm, e0z = q0.z - x0.z*nrm, e0w = q0.w - x0.w*nrm;
    float e1x = q1.x - x1.x*nrm, e1y = q1.y - x1.y*nrm, e1z = q1.z - x1.z*nrm, e1w = q1.w - x1.w*nrm;
    float cs = e0x*e0x + e0y*e0y + e0z*e0z + e0w*e0w
             + e1x*e1x + e1y*e1y + e1z*e1z + e1w*e1w;
    #pragma unroll
    for (int o = 16; o; o >>= 1) cs += __shfl_xor_sync(~0u, cs, o);
    if (lane == 0) atomicAdd(&g_acc, (double)cs);

    __syncthreads();

    // coalesced transposed write: warp w writes d rows [w*8, w*8+8)
    #pragma unroll
    for (int j = 0; j < 8; j++) {
        int d = wid * 8 + j;
        out[(size_t)b * DD * LL + (size_t)d * LL + l0 + lane] = tile[d][lane];
    }
}

__global__ void finalize_kernel(float* __restrict__ out, int out_size) {
    long q = (long)BB * DD * LL;
    float loss = (float)(0.25 * g_acc / (double)((long)NN * DD));
    for (long i = q + threadIdx.x; i < (long)out_size; i += blockDim.x) out[i] = loss;
}

// ------------------------------------------------------------------
extern "C" void kernel_launch(void* const* d_in, const int* in_sizes, int n_in,
                              void* d_out, int out_size) {
    const float* x  = (const float*)d_in[0];   // [4,256,4096]
    const float* cb = (const float*)d_in[1];   // [8192,256]
    float* out = (float*)d_out;

    static int attr_set = 0;
    if (!attr_set) {
        cudaFuncSetAttribute(gemm_topk_kernel,
                             cudaFuncAttributeMaxDynamicSharedMemorySize, GSMEM);
        attr_set = 1;
    }

    prep_kernel<<<1536, 256>>>(cb, x);
    gemm_topk_kernel<<<dim3(KSPLIT, NN / BM), 256, GSMEM>>>();
    rotate_out_kernel<<<dim3(LL / 32, BB), 1024>>>(out);
    finalize_kernel<<<1, 256>>>(out, out_size);
}